// round 1
// baseline (speedup 1.0000x reference)
#include <cuda_runtime.h>
#include <cstdint>

#define B_ 2
#define S_ 2048
#define D_ 1024
#define H_ 16
#define HD_ 64

// Scratch (allocation-free rule: device globals)
__device__ float g_qkv[3 * B_ * H_ * S_ * HD_];   // [which][b][h][s][hd]  48MB
__device__ float g_vals[B_ * S_ * D_];            // scrambled attn output 16MB

// ---------------------------------------------------------------------------
// Tiled SGEMM: C[M,N] = A[M,K] @ B[K,N] + bias, 128x128 tile, BK=16,
// 256 threads, 8x8 micro-tile per thread.
// MODE 0: A = x, epilogue scatters into g_qkv ([3][B][H][S][64] layout)
// MODE 1: A = g_vals, epilogue writes C row-major (d_out)
// ---------------------------------------------------------------------------
template <int MODE>
__global__ void __launch_bounds__(256) gemm128(
    const float* __restrict__ A, const float* __restrict__ Bm,
    const float* __restrict__ bias, float* __restrict__ C,
    int M, int N, int K)
{
    __shared__ float As[16][132];   // transposed A tile: As[k][m]
    __shared__ float Bs[16][128];   // Bs[k][n]

    const int tid = threadIdx.x;
    const int tx = tid & 15;        // 0..15 -> n micro
    const int ty = tid >> 4;        // 0..15 -> m micro
    const int bx = blockIdx.x;      // n tile
    const int by = blockIdx.y;      // m tile

    const float* Ap = (MODE == 1) ? g_vals : A;

    float acc[8][8];
#pragma unroll
    for (int i = 0; i < 8; i++)
#pragma unroll
        for (int j = 0; j < 8; j++) acc[i][j] = 0.0f;

    const int arow = tid >> 2;           // 0..63
    const int acol = (tid & 3) << 2;     // 0,4,8,12
    const int brow = tid >> 5;           // 0..7
    const int bcol = (tid & 31) << 2;    // 0..124

    for (int kb = 0; kb < K; kb += 16) {
        // load A tile (128 x 16), store transposed
#pragma unroll
        for (int r = 0; r < 2; r++) {
            int row = arow + r * 64;
            float4 a = *(const float4*)(Ap + (size_t)(by * 128 + row) * K + kb + acol);
            As[acol + 0][row] = a.x;
            As[acol + 1][row] = a.y;
            As[acol + 2][row] = a.z;
            As[acol + 3][row] = a.w;
        }
        // load B tile (16 x 128)
#pragma unroll
        for (int r = 0; r < 2; r++) {
            int row = brow + r * 8;
            *(float4*)&Bs[row][bcol] =
                *(const float4*)(Bm + (size_t)(kb + row) * N + bx * 128 + bcol);
        }
        __syncthreads();

#pragma unroll
        for (int k = 0; k < 16; k++) {
            float4 a0 = *(const float4*)&As[k][ty * 8];
            float4 a1 = *(const float4*)&As[k][ty * 8 + 4];
            float4 b0 = *(const float4*)&Bs[k][tx * 8];
            float4 b1 = *(const float4*)&Bs[k][tx * 8 + 4];
            float av[8] = {a0.x, a0.y, a0.z, a0.w, a1.x, a1.y, a1.z, a1.w};
            float bv[8] = {b0.x, b0.y, b0.z, b0.w, b1.x, b1.y, b1.z, b1.w};
#pragma unroll
            for (int i = 0; i < 8; i++)
#pragma unroll
                for (int j = 0; j < 8; j++)
                    acc[i][j] = fmaf(av[i], bv[j], acc[i][j]);
        }
        __syncthreads();
    }

    if (MODE == 0) {
        // scatter into g_qkv: n -> (which, h, hd); m -> (b, s)
#pragma unroll
        for (int i = 0; i < 8; i++) {
            int m = by * 128 + ty * 8 + i;
            int b = m >> 11;          // /2048
            int s = m & 2047;
#pragma unroll
            for (int j = 0; j < 8; j++) {
                int n = bx * 128 + tx * 8 + j;
                float v = acc[i][j] + bias[n];
                int which = n >> 10;
                int d = n & 1023;
                int h = d >> 6;
                int hd = d & 63;
                g_qkv[((((which * B_ + b) * H_ + h) * S_) + s) * HD_ + hd] = v;
            }
        }
    } else {
#pragma unroll
        for (int i = 0; i < 8; i++) {
            int m = by * 128 + ty * 8 + i;
#pragma unroll
            for (int jj = 0; jj < 2; jj++) {
                int n = bx * 128 + tx * 8 + jj * 4;
                float4 v;
                v.x = acc[i][jj * 4 + 0] + bias[n + 0];
                v.y = acc[i][jj * 4 + 1] + bias[n + 1];
                v.z = acc[i][jj * 4 + 2] + bias[n + 2];
                v.w = acc[i][jj * 4 + 3] + bias[n + 3];
                *(float4*)(C + (size_t)m * N + n) = v;
            }
        }
    }
}

// ---------------------------------------------------------------------------
// Flash attention: one CTA per (b, h, 64-query tile). 256 threads.
// Thread grid 16x16: ty -> 4 query rows, tx -> 4 key cols / 4 hd cols.
// smem: Qt[hd][q], Kt[hd][k] (transposed, outer-product GEMM1),
//       Vs[k][hd], Pt[k][q]. All pitch 68 floats (float4-aligned rows).
// ---------------------------------------------------------------------------
#define PITCH 68

__global__ void __launch_bounds__(256) attn_kernel(const float* __restrict__ mask)
{
    extern __shared__ float sm[];
    float* Qt = sm;                  // [64][PITCH]
    float* Kt = sm + 64 * PITCH;     // [64][PITCH]
    float* Vs = sm + 2 * 64 * PITCH; // [64][PITCH]
    float* Pt = sm + 3 * 64 * PITCH; // [64][PITCH]

    const int q0 = blockIdx.x * 64;
    const int h = blockIdx.y;
    const int b = blockIdx.z;
    const int tid = threadIdx.x;
    const int tx = tid & 15;
    const int ty = tid >> 4;

    const float* Qg = g_qkv + (((size_t)(0 * B_ + b) * H_ + h) * S_ + q0) * HD_;
    const float* Kg = g_qkv + (((size_t)(1 * B_ + b) * H_ + h) * S_) * HD_;
    const float* Vg = g_qkv + (((size_t)(2 * B_ + b) * H_ + h) * S_) * HD_;

    // Load Q tile, transposed to [hd][q]
#pragma unroll
    for (int r = 0; r < 4; r++) {
        int idx = tid + 256 * r;
        int q = idx >> 4;
        int c = (idx & 15) << 2;
        float4 v = *(const float4*)(Qg + q * HD_ + c);
        Qt[(c + 0) * PITCH + q] = v.x;
        Qt[(c + 1) * PITCH + q] = v.y;
        Qt[(c + 2) * PITCH + q] = v.z;
        Qt[(c + 3) * PITCH + q] = v.w;
    }

    float m_i[4], l_i[4], acc[4][4];
#pragma unroll
    for (int i = 0; i < 4; i++) {
        m_i[i] = -1e30f;
        l_i[i] = 0.0f;
#pragma unroll
        for (int j = 0; j < 4; j++) acc[i][j] = 0.0f;
    }

    const float scale = 0.125f;  // 1/sqrt(64)

    for (int k0 = 0; k0 < S_; k0 += 64) {
        // Load K (transposed) and V (natural) tiles
#pragma unroll
        for (int r = 0; r < 4; r++) {
            int idx = tid + 256 * r;
            int kk = idx >> 4;
            int c = (idx & 15) << 2;
            float4 kv = *(const float4*)(Kg + (size_t)(k0 + kk) * HD_ + c);
            Kt[(c + 0) * PITCH + kk] = kv.x;
            Kt[(c + 1) * PITCH + kk] = kv.y;
            Kt[(c + 2) * PITCH + kk] = kv.z;
            Kt[(c + 3) * PITCH + kk] = kv.w;
            float4 vv = *(const float4*)(Vg + (size_t)(k0 + kk) * HD_ + c);
            *(float4*)&Vs[kk * PITCH + c] = vv;
        }
        __syncthreads();

        // GEMM1: S[q][k] = sum_d Q[q][d] * K[k][d]  (outer product over d)
        float s[4][4];
#pragma unroll
        for (int i = 0; i < 4; i++)
#pragma unroll
            for (int j = 0; j < 4; j++) s[i][j] = 0.0f;

#pragma unroll
        for (int d = 0; d < 64; d++) {
            float4 qv = *(const float4*)&Qt[d * PITCH + ty * 4];
            float4 kv = *(const float4*)&Kt[d * PITCH + tx * 4];
            float qa[4] = {qv.x, qv.y, qv.z, qv.w};
            float ka[4] = {kv.x, kv.y, kv.z, kv.w};
#pragma unroll
            for (int i = 0; i < 4; i++)
#pragma unroll
                for (int j = 0; j < 4; j++)
                    s[i][j] = fmaf(qa[i], ka[j], s[i][j]);
        }

        // mask + scale + online softmax per query row
#pragma unroll
        for (int i = 0; i < 4; i++) {
            int q = q0 + ty * 4 + i;
            float4 mk = *(const float4*)(mask + ((size_t)b * S_ + q) * S_ + k0 + tx * 4);
            s[i][0] = s[i][0] * scale + mk.x * (-1e9f);
            s[i][1] = s[i][1] * scale + mk.y * (-1e9f);
            s[i][2] = s[i][2] * scale + mk.z * (-1e9f);
            s[i][3] = s[i][3] * scale + mk.w * (-1e9f);

            float mx = fmaxf(fmaxf(s[i][0], s[i][1]), fmaxf(s[i][2], s[i][3]));
#pragma unroll
            for (int o = 1; o < 16; o <<= 1)
                mx = fmaxf(mx, __shfl_xor_sync(0xffffffffu, mx, o));

            float mnew = fmaxf(m_i[i], mx);
            float corr = __expf(m_i[i] - mnew);
            float psum = 0.0f;
#pragma unroll
            for (int j = 0; j < 4; j++) {
                s[i][j] = __expf(s[i][j] - mnew);
                psum += s[i][j];
            }
#pragma unroll
            for (int o = 1; o < 16; o <<= 1)
                psum += __shfl_xor_sync(0xffffffffu, psum, o);

            l_i[i] = l_i[i] * corr + psum;
            m_i[i] = mnew;
#pragma unroll
            for (int j = 0; j < 4; j++) acc[i][j] *= corr;

            // write P transposed: Pt[k][q]
#pragma unroll
            for (int j = 0; j < 4; j++)
                Pt[(tx * 4 + j) * PITCH + ty * 4 + i] = s[i][j];
        }
        __syncthreads();

        // GEMM2: O[q][hd] += sum_k P[q][k] * V[k][hd]  (outer product over k)
#pragma unroll
        for (int kk = 0; kk < 64; kk++) {
            float4 pv = *(const float4*)&Pt[kk * PITCH + ty * 4];
            float4 vv = *(const float4*)&Vs[kk * PITCH + tx * 4];
            float pa[4] = {pv.x, pv.y, pv.z, pv.w};
            float va[4] = {vv.x, vv.y, vv.z, vv.w};
#pragma unroll
            for (int i = 0; i < 4; i++)
#pragma unroll
                for (int j = 0; j < 4; j++)
                    acc[i][j] = fmaf(pa[i], va[j], acc[i][j]);
        }
        __syncthreads();
    }

    // Epilogue: normalize, write scrambled layout
    // L = ((h*B + b)*S + q)*64 + hd   (faithful to reference's transpose+reshape)
#pragma unroll
    for (int i = 0; i < 4; i++) {
        float inv = 1.0f / l_i[i];
        int q = q0 + ty * 4 + i;
        float4 v;
        v.x = acc[i][0] * inv;
        v.y = acc[i][1] * inv;
        v.z = acc[i][2] * inv;
        v.w = acc[i][3] * inv;
        *(float4*)(g_vals + (((size_t)h * B_ + b) * S_ + q) * HD_ + tx * 4) = v;
    }
}

// ---------------------------------------------------------------------------
extern "C" void kernel_launch(void* const* d_in, const int* in_sizes, int n_in,
                              void* d_out, int out_size)
{
    const float* x    = (const float*)d_in[0];
    const float* mask = (const float*)d_in[1];
    const float* Wqkv = (const float*)d_in[2];
    const float* bqkv = (const float*)d_in[3];
    const float* Wo   = (const float*)d_in[4];
    const float* bo   = (const float*)d_in[5];
    float* out = (float*)d_out;

    const int M = B_ * S_;  // 4096

    // 1) QKV GEMM (scatter epilogue into g_qkv)
    gemm128<0><<<dim3(3 * D_ / 128, M / 128), 256>>>(x, Wqkv, bqkv, nullptr,
                                                     M, 3 * D_, D_);

    // 2) Flash attention
    int smem = 4 * 64 * PITCH * (int)sizeof(float);  // 69632 B
    cudaFuncSetAttribute(attn_kernel, cudaFuncAttributeMaxDynamicSharedMemorySize, smem);
    attn_kernel<<<dim3(S_ / 64, H_, B_), 256, smem>>>(mask);

    // 3) Output projection
    gemm128<1><<<dim3(D_ / 128, M / 128), 256>>>(nullptr, Wo, bo, out,
                                                 M, D_, D_);
}